// round 16
// baseline (speedup 1.0000x reference)
#include <cuda_runtime.h>
#include <math.h>
#include <stdint.h>

#define N_NODES 2048
#define IN_F    128
#define OUT_F   32
#define KC      256
#define NTILES  (N_NODES / KC)          // 8
#define NSTEP   (KC / 32)               // 8
#define WARPS   5
#define THREADS (WARPS * 32)            // 160
#define ROWS_CTA 10
#define GRID    205                     // 205*10 = 2050 >= 2048, 2 CTAs/SM
#define LOG2E 1.4426950408889634f

// Stage: [0,16K) fp16 score tile | [16K,48K) fp32 agg tile | [48K,+1K) dk
#define SC_BYTES    (KC * OUT_F * 2)          // 16384
#define AG_BYTES    (KC * OUT_F * 4)          // 32768
#define DK_OFF      (SC_BYTES + AG_BYTES)     // 49152
#define STAGE_BYTES (DK_OFF + KC * 4)         // 50176
#define SMEM_BYTES  (2 * STAGE_BYTES)         // 100352 (x2 CTAs = 196KB < 228KB)

__device__ float          g_Wh1[N_NODES * OUT_F];   // fp32 Wh1 (agg tile)
__device__ unsigned short g_Wh2h[N_NODES * OUT_F];  // fp16 Wh2 (score tile)
__device__ float          g_c6L[N_NODES];           // log2e*0.6*dot(a,Wh1[i])
__device__ float          g_dk6L[N_NODES];          // log2e*0.6*dot(a,Wh2[k])

// ---------------------------------------------------------------------------
// Kernel 1: projections + constants + fp16 Wh2. 512 CTAs x 128 thr.
// ---------------------------------------------------------------------------
__global__ __launch_bounds__(128) void gat_gemm_kernel(
    const float* __restrict__ h, const float* __restrict__ W,
    const float* __restrict__ a)
{
    __shared__ float Ws[2 * IN_F * OUT_F];
    __shared__ float hs[4][IN_F];
    const int tid = threadIdx.x, w = tid >> 5, lane = tid & 31;
    const int row0 = blockIdx.x * 4;
    {
        const uint32_t wsb = (uint32_t)__cvta_generic_to_shared(Ws);
        const uint32_t hsb = (uint32_t)__cvta_generic_to_shared(&hs[0][0]);
        const float4* gw = (const float4*)W;
        const float4* gh = (const float4*)(h + (size_t)row0 * IN_F);
#pragma unroll
        for (int i = 0; i < 16; ++i)
            asm volatile("cp.async.cg.shared.global [%0], [%1], 16;"
                         :: "r"(wsb + (uint32_t)((tid + i * 128) * 16)),
                            "l"(gw + tid + i * 128) : "memory");
        asm volatile("cp.async.cg.shared.global [%0], [%1], 16;"
                     :: "r"(hsb + (uint32_t)(tid * 16)), "l"(gh + tid) : "memory");
        asm volatile("cp.async.commit_group;" ::: "memory");
        asm volatile("cp.async.wait_group 0;" ::: "memory");
    }
    __syncthreads();

    const int row = row0 + w;
    float wh1 = 0.f, wh2 = 0.f;
#pragma unroll 8
    for (int j = 0; j < IN_F; ++j) {
        const float hv = hs[w][j];
        wh1 = fmaf(hv, Ws[j * OUT_F + lane], wh1);
        wh2 = fmaf(hv, Ws[(IN_F + j) * OUT_F + lane], wh2);
    }
    g_Wh1[row * OUT_F + lane] = wh1;
    unsigned short h2;
    asm("cvt.rn.f16.f32 %0, %1;" : "=h"(h2) : "f"(wh2));
    g_Wh2h[row * OUT_F + lane] = h2;

    const float av = __ldg(a + lane);
    float c = av * wh1, d = av * wh2;
#pragma unroll
    for (int o = 16; o; o >>= 1) {
        c += __shfl_xor_sync(0xffffffffu, c, o);
        d += __shfl_xor_sync(0xffffffffu, d, o);
    }
    if (lane == 0) {
        g_c6L[row]  = (0.6f * LOG2E) * c;
        g_dk6L[row] = (0.6f * LOG2E) * d;
    }
}

// ---------------------------------------------------------------------------
// Kernel 2: fused score(fp16x2) + softmax + agg(fp32x2) + ELU.
// 160 thr x 205 CTAs, 2 CTAs/SM (10 warps), KC=256, adj pipelined 2 ahead.
// ---------------------------------------------------------------------------
extern __shared__ float smem2[];

__device__ __forceinline__ void issue_tile(int t, uint32_t smem_u, int tid)
{
    const uint32_t sb = smem_u + (t & 1) * STAGE_BYTES;
    // fp16 score tile: KC rows x 64B, swizzle q^((kk>>1)&3)
    const float4* g2 = (const float4*)(g_Wh2h + (size_t)t * (KC * OUT_F));
    for (int i = tid; i < KC * 4; i += THREADS) {
        int kk = i >> 2, q = i & 3;
        uint32_t soff = (uint32_t)(kk * 64 + ((q ^ ((kk >> 1) & 3)) << 4));
        asm volatile("cp.async.cg.shared.global [%0], [%1], 16;"
                     :: "r"(sb + soff), "l"(g2 + i) : "memory");
    }
    // fp32 agg tile: KC rows x 128B, swizzle f4^(kk&7)
    const float4* g1 = ((const float4*)g_Wh1) + t * (KC * 8);
    for (int i = tid; i < KC * 8; i += THREADS) {
        int kk = i >> 3, f4 = i & 7;
        uint32_t soff = (uint32_t)(((kk << 3) | (f4 ^ (kk & 7))) << 4);
        asm volatile("cp.async.cg.shared.global [%0], [%1], 16;"
                     :: "r"(sb + SC_BYTES + soff), "l"(g1 + i) : "memory");
    }
    const float* gd = g_dk6L + t * KC;
    for (int i = tid; i < KC; i += THREADS)
        asm volatile("cp.async.ca.shared.global [%0], [%1], 4;"
                     :: "r"(sb + DK_OFF + (uint32_t)(i * 4)), "l"(gd + i) : "memory");
    asm volatile("cp.async.commit_group;" ::: "memory");
}

__global__ __launch_bounds__(THREADS, 2) void gat_attn_kernel(
    const int* __restrict__ adj, const float* __restrict__ a,
    float* __restrict__ out)
{
    const int tid = threadIdx.x, w = tid >> 5, lane = tid & 31;
    const uint32_t smem_u = (uint32_t)__cvta_generic_to_shared(smem2);
    int row0 = blockIdx.x * ROWS_CTA + 2 * w;
    int row1 = row0 + 1;
    if (row1 >= N_NODES) { row0 = N_NODES - 2; row1 = N_NODES - 1; }

    // fp16x2 score operands; fp32x2 accumulators
    uint32_t wh1pH[2][16], a4LH[16];
    unsigned long long acc[2][16];
#pragma unroll
    for (int j = 0; j < 16; ++j) {
        float a0 = __ldg(a + 2 * j), a1 = __ldg(a + 2 * j + 1);
        float A0 = (0.4f * LOG2E) * a0, A1 = (0.4f * LOG2E) * a1;
        float x0 = g_Wh1[row0 * OUT_F + 2 * j], x1 = g_Wh1[row0 * OUT_F + 2 * j + 1];
        float y0 = g_Wh1[row1 * OUT_F + 2 * j], y1 = g_Wh1[row1 * OUT_F + 2 * j + 1];
        asm("{.reg .f16 l, hh; cvt.rn.f16.f32 l, %1; cvt.rn.f16.f32 hh, %2; mov.b32 %0, {l, hh};}"
            : "=r"(a4LH[j]) : "f"(A0), "f"(A1));
        asm("{.reg .f16 l, hh; cvt.rn.f16.f32 l, %1; cvt.rn.f16.f32 hh, %2; mov.b32 %0, {l, hh};}"
            : "=r"(wh1pH[0][j]) : "f"(x0), "f"(x1));
        asm("{.reg .f16 l, hh; cvt.rn.f16.f32 l, %1; cvt.rn.f16.f32 hh, %2; mov.b32 %0, {l, hh};}"
            : "=r"(wh1pH[1][j]) : "f"(y0), "f"(y1));
        acc[0][j] = 0ull; acc[1][j] = 0ull;
    }
    const float c0 = g_c6L[row0], c1 = g_c6L[row1];
    float lsum0 = 0.f, lsum1 = 0.f;

    // Per-lane adjacency, pipelined 2 steps ahead.
    const int* adjr0 = adj + (size_t)row0 * N_NODES + lane;
    const int* adjr1 = adj + (size_t)row1 * N_NODES + lane;
    int va0[2], va1[2];
    va0[0] = __ldg(adjr0);       va0[1] = __ldg(adjr0 + 32);
    va1[0] = __ldg(adjr1);       va1[1] = __ldg(adjr1 + 32);

    issue_tile(0, smem_u, tid);

#pragma unroll 1
    for (int t = 0; t < NTILES; ++t) {
        __syncthreads();
        if (t + 1 < NTILES) {
            issue_tile(t + 1, smem_u, tid);
            asm volatile("cp.async.wait_group 1;" ::: "memory");
        } else {
            asm volatile("cp.async.wait_group 0;" ::: "memory");
        }
        __syncthreads();

        const uint32_t sb = smem_u + (t & 1) * STAGE_BYTES;
        const float* sdk = (const float*)((const char*)smem2 + (t & 1) * STAGE_BYTES + DK_OFF);

#pragma unroll 4
        for (int step = 0; step < NSTEP; ++step) {
            const int kk = (step << 5) | lane;
            const int av0 = va0[step & 1], av1 = va1[step & 1];
            // prefetch adj for step+2 (wraps harmlessly at the end)
            const int nko = ((t << 8) + ((step + 2) << 5)) & (N_NODES - 1);
            va0[step & 1] = __ldg(adjr0 + nko);
            va1[step & 1] = __ldg(adjr1 + nko);
            const float dkv = sdk[kk];

            // ---- Score (fp16x2): 4 swizzled LDS.128 -> 16 fp16x2 ----
            uint32_t hh[16];
            {
                const uint32_t rb = sb + (uint32_t)(kk * 64);
                const int sw = (kk >> 1) & 3;
#pragma unroll
                for (int q = 0; q < 4; ++q)
                    asm volatile("ld.shared.v4.b32 {%0, %1, %2, %3}, [%4];"
                                 : "=r"(hh[4*q]), "=r"(hh[4*q+1]), "=r"(hh[4*q+2]), "=r"(hh[4*q+3])
                                 : "r"(rb + (uint32_t)((q ^ sw) << 4)));
            }
            uint32_t s0[4] = {0,0,0,0}, s1[4] = {0,0,0,0};
#pragma unroll
            for (int j = 0; j < 16; ++j) {
                uint32_t t0, t1;
                asm("add.rn.f16x2 %0, %1, %2;" : "=r"(t0) : "r"(wh1pH[0][j]), "r"(hh[j]));
                t0 &= 0x7fff7fffu;
                asm("fma.rn.f16x2 %0, %1, %2, %0;" : "+r"(s0[j & 3]) : "r"(a4LH[j]), "r"(t0));
                asm("add.rn.f16x2 %0, %1, %2;" : "=r"(t1) : "r"(wh1pH[1][j]), "r"(hh[j]));
                t1 &= 0x7fff7fffu;
                asm("fma.rn.f16x2 %0, %1, %2, %0;" : "+r"(s1[j & 3]) : "r"(a4LH[j]), "r"(t1));
            }
            float p0, p1;
            {
                uint32_t u; float lo, hi, e;
                asm("add.rn.f16x2 %0, %1, %2;" : "=r"(u) : "r"(s0[0]), "r"(s0[1]));
                asm("add.rn.f16x2 %0, %1, %2;" : "=r"(s0[2]) : "r"(s0[2]), "r"(s0[3]));
                asm("add.rn.f16x2 %0, %1, %2;" : "=r"(u) : "r"(u), "r"(s0[2]));
                asm("{.reg .f16 l, hh; mov.b32 {l, hh}, %2; cvt.f32.f16 %0, l; cvt.f32.f16 %1, hh;}"
                    : "=f"(lo), "=f"(hi) : "r"(u));
                e = (c0 + dkv) + (lo + hi);
                asm("ex2.approx.f32 %0, %1;" : "=f"(p0) : "f"(e));
                p0 = (av0 > 0) ? p0 : 0.f;
                asm("add.rn.f16x2 %0, %1, %2;" : "=r"(u) : "r"(s1[0]), "r"(s1[1]));
                asm("add.rn.f16x2 %0, %1, %2;" : "=r"(s1[2]) : "r"(s1[2]), "r"(s1[3]));
                asm("add.rn.f16x2 %0, %1, %2;" : "=r"(u) : "r"(u), "r"(s1[2]));
                asm("{.reg .f16 l, hh; mov.b32 {l, hh}, %2; cvt.f32.f16 %0, l; cvt.f32.f16 %1, hh;}"
                    : "=f"(lo), "=f"(hi) : "r"(u));
                e = (c1 + dkv) + (lo + hi);
                asm("ex2.approx.f32 %0, %1;" : "=f"(p1) : "f"(e));
                p1 = (av1 > 0) ? p1 : 0.f;
            }
            lsum0 += p0; lsum1 += p1;
            unsigned long long p20, p21;
            asm("mov.b64 %0, {%1, %1};" : "=l"(p20) : "f"(p0));
            asm("mov.b64 %0, {%1, %1};" : "=l"(p21) : "f"(p1));

            // ---- Aggregate (fp32x2): 8 swizzled LDS.128 ----
            const uint32_t rb1 = sb + SC_BYTES + (uint32_t)(kk << 7);
            const int sx = kk & 7;
#pragma unroll
            for (int f4 = 0; f4 < 8; ++f4) {
                unsigned long long v0, v1;
                asm volatile("ld.shared.v2.b64 {%0, %1}, [%2];"
                             : "=l"(v0), "=l"(v1) : "r"(rb1 + (uint32_t)((f4 ^ sx) << 4)));
                asm("fma.rn.f32x2 %0, %1, %2, %0;" : "+l"(acc[0][2*f4])   : "l"(p20), "l"(v0));
                asm("fma.rn.f32x2 %0, %1, %2, %0;" : "+l"(acc[0][2*f4+1]) : "l"(p20), "l"(v1));
                asm("fma.rn.f32x2 %0, %1, %2, %0;" : "+l"(acc[1][2*f4])   : "l"(p21), "l"(v0));
                asm("fma.rn.f32x2 %0, %1, %2, %0;" : "+l"(acc[1][2*f4+1]) : "l"(p21), "l"(v1));
            }
        }
    }

    // ---- Epilogue: cross-lane reduce, divide, ELU ----
    float L0 = lsum0, L1 = lsum1;
#pragma unroll
    for (int o = 16; o; o >>= 1) {
        L0 += __shfl_xor_sync(0xffffffffu, L0, o);
        L1 += __shfl_xor_sync(0xffffffffu, L1, o);
    }
    __syncthreads();
    float* red = smem2 + w * (32 * 33);
#pragma unroll 1
    for (int r = 0; r < 2; ++r) {
#pragma unroll
        for (int j = 0; j < 16; ++j) {
            float lo, hi;
            asm("mov.b64 {%0, %1}, %2;" : "=f"(lo), "=f"(hi) : "l"(acc[r][j]));
            red[lane * 33 + 2 * j]     = lo;
            red[lane * 33 + 2 * j + 1] = hi;
        }
        __syncwarp();
        float tot = 0.f;
#pragma unroll 8
        for (int jj = 0; jj < 32; ++jj) tot += red[jj * 33 + lane];
        const float L = r ? L1 : L0;
        const int row = r ? row1 : row0;
        const float hv = tot / L;
        out[row * OUT_F + lane] = hv > 0.f ? hv : expm1f(hv);
        __syncwarp();
    }
}

// ---------------------------------------------------------------------------
extern "C" void kernel_launch(void* const* d_in, const int* in_sizes, int n_in,
                              void* d_out, int out_size)
{
    const float* h   = (const float*)d_in[0];
    const int*   adj = (const int*)  d_in[1];
    const float* W   = (const float*)d_in[2];
    const float* a   = (const float*)d_in[3];
    float*       out = (float*)d_out;

    gat_gemm_kernel<<<N_NODES / 4, 128>>>(h, W, a);

    cudaFuncSetAttribute(gat_attn_kernel,
                         cudaFuncAttributeMaxDynamicSharedMemorySize, SMEM_BYTES);
    gat_attn_kernel<<<GRID, THREADS, SMEM_BYTES>>>(adj, a, out);
}

// round 17
// speedup vs baseline: 1.4714x; 1.4714x over previous
#include <cuda_runtime.h>
#include <math.h>
#include <stdint.h>

#define N_NODES 2048
#define IN_F    128
#define OUT_F   32
#define KC      256
#define NTILES  (N_NODES / KC)          // 8
#define NSTEP   (KC / 32)               // 8
#define WARPS   4
#define THREADS (WARPS * 32)            // 128
#define ROWS_CTA 8
#define GRID    296                     // exactly 2*148 -> 2 CTAs on every SM
#define LOG2E 1.4426950408889634f

// Stage: [0,16K) fp16 score tile | [16K,48K) fp32 agg tile | [48K,+1K) dk
#define SC_BYTES    (KC * OUT_F * 2)          // 16384
#define AG_BYTES    (KC * OUT_F * 4)          // 32768
#define DK_OFF      (SC_BYTES + AG_BYTES)     // 49152
#define STAGE_BYTES (DK_OFF + KC * 4)         // 50176
#define SMEM_BYTES  (2 * STAGE_BYTES)         // 100352 (x2 CTAs = 196KB < 228KB)

__device__ float          g_Wh1[N_NODES * OUT_F];   // fp32 Wh1 (agg tile)
__device__ unsigned short g_Wh2h[N_NODES * OUT_F];  // fp16 Wh2 (score tile)
__device__ float          g_c6L[N_NODES];           // log2e*0.6*dot(a,Wh1[i])
__device__ float          g_dk6L[N_NODES];          // log2e*0.6*dot(a,Wh2[k])

// ---------------------------------------------------------------------------
// Kernel 1: projections + constants + fp16 Wh2. 512 CTAs x 128 thr.
// ---------------------------------------------------------------------------
__global__ __launch_bounds__(128) void gat_gemm_kernel(
    const float* __restrict__ h, const float* __restrict__ W,
    const float* __restrict__ a)
{
    __shared__ float Ws[2 * IN_F * OUT_F];
    __shared__ float hs[4][IN_F];
    const int tid = threadIdx.x, w = tid >> 5, lane = tid & 31;
    const int row0 = blockIdx.x * 4;
    {
        const uint32_t wsb = (uint32_t)__cvta_generic_to_shared(Ws);
        const uint32_t hsb = (uint32_t)__cvta_generic_to_shared(&hs[0][0]);
        const float4* gw = (const float4*)W;
        const float4* gh = (const float4*)(h + (size_t)row0 * IN_F);
#pragma unroll
        for (int i = 0; i < 16; ++i)
            asm volatile("cp.async.cg.shared.global [%0], [%1], 16;"
                         :: "r"(wsb + (uint32_t)((tid + i * 128) * 16)),
                            "l"(gw + tid + i * 128) : "memory");
        asm volatile("cp.async.cg.shared.global [%0], [%1], 16;"
                     :: "r"(hsb + (uint32_t)(tid * 16)), "l"(gh + tid) : "memory");
        asm volatile("cp.async.commit_group;" ::: "memory");
        asm volatile("cp.async.wait_group 0;" ::: "memory");
    }
    __syncthreads();

    const int row = row0 + w;
    float wh1 = 0.f, wh2 = 0.f;
#pragma unroll 8
    for (int j = 0; j < IN_F; ++j) {
        const float hv = hs[w][j];
        wh1 = fmaf(hv, Ws[j * OUT_F + lane], wh1);
        wh2 = fmaf(hv, Ws[(IN_F + j) * OUT_F + lane], wh2);
    }
    g_Wh1[row * OUT_F + lane] = wh1;
    unsigned short h2;
    asm("cvt.rn.f16.f32 %0, %1;" : "=h"(h2) : "f"(wh2));
    g_Wh2h[row * OUT_F + lane] = h2;

    const float av = __ldg(a + lane);
    float c = av * wh1, d = av * wh2;
#pragma unroll
    for (int o = 16; o; o >>= 1) {
        c += __shfl_xor_sync(0xffffffffu, c, o);
        d += __shfl_xor_sync(0xffffffffu, d, o);
    }
    if (lane == 0) {
        g_c6L[row]  = (0.6f * LOG2E) * c;
        g_dk6L[row] = (0.6f * LOG2E) * d;
    }
}

// ---------------------------------------------------------------------------
// Kernel 2: fused score(fp16x2) + softmax + agg(fp32x2) + ELU.
// 128 thr x 296 CTAs = exactly 2 CTAs / SM (8 warps), no reg cap.
// ---------------------------------------------------------------------------
extern __shared__ float smem2[];

__device__ __forceinline__ void issue_tile(int t, uint32_t smem_u, int tid)
{
    const uint32_t sb = smem_u + (t & 1) * STAGE_BYTES;
    // fp16 score tile: KC rows x 64B, swizzle q^((kk>>1)&3)
    const float4* g2 = (const float4*)(g_Wh2h + (size_t)t * (KC * OUT_F));
    for (int i = tid; i < KC * 4; i += THREADS) {
        int kk = i >> 2, q = i & 3;
        uint32_t soff = (uint32_t)(kk * 64 + ((q ^ ((kk >> 1) & 3)) << 4));
        asm volatile("cp.async.cg.shared.global [%0], [%1], 16;"
                     :: "r"(sb + soff), "l"(g2 + i) : "memory");
    }
    // fp32 agg tile: KC rows x 128B, swizzle f4^(kk&7)
    const float4* g1 = ((const float4*)g_Wh1) + t * (KC * 8);
    for (int i = tid; i < KC * 8; i += THREADS) {
        int kk = i >> 3, f4 = i & 7;
        uint32_t soff = (uint32_t)(((kk << 3) | (f4 ^ (kk & 7))) << 4);
        asm volatile("cp.async.cg.shared.global [%0], [%1], 16;"
                     :: "r"(sb + SC_BYTES + soff), "l"(g1 + i) : "memory");
    }
    const float* gd = g_dk6L + t * KC;
    for (int i = tid; i < KC; i += THREADS)
        asm volatile("cp.async.ca.shared.global [%0], [%1], 4;"
                     :: "r"(sb + DK_OFF + (uint32_t)(i * 4)), "l"(gd + i) : "memory");
    asm volatile("cp.async.commit_group;" ::: "memory");
}

__global__ __launch_bounds__(THREADS, 2) void gat_attn_kernel(
    const int* __restrict__ adj, const float* __restrict__ a,
    float* __restrict__ out)
{
    const int tid = threadIdx.x, w = tid >> 5, lane = tid & 31;
    const uint32_t smem_u = (uint32_t)__cvta_generic_to_shared(smem2);
    int row0 = blockIdx.x * ROWS_CTA + 2 * w;
    int row1 = row0 + 1;
    if (row1 >= N_NODES) { row0 = N_NODES - 2; row1 = N_NODES - 1; }  // dup tail

    // fp16x2 score operands; fp32x2 accumulators
    uint32_t wh1pH[2][16], a4LH[16];
    unsigned long long acc[2][16];
#pragma unroll
    for (int j = 0; j < 16; ++j) {
        float a0 = __ldg(a + 2 * j), a1 = __ldg(a + 2 * j + 1);
        float A0 = (0.4f * LOG2E) * a0, A1 = (0.4f * LOG2E) * a1;
        float x0 = g_Wh1[row0 * OUT_F + 2 * j], x1 = g_Wh1[row0 * OUT_F + 2 * j + 1];
        float y0 = g_Wh1[row1 * OUT_F + 2 * j], y1 = g_Wh1[row1 * OUT_F + 2 * j + 1];
        asm("{.reg .f16 l, hh; cvt.rn.f16.f32 l, %1; cvt.rn.f16.f32 hh, %2; mov.b32 %0, {l, hh};}"
            : "=r"(a4LH[j]) : "f"(A0), "f"(A1));
        asm("{.reg .f16 l, hh; cvt.rn.f16.f32 l, %1; cvt.rn.f16.f32 hh, %2; mov.b32 %0, {l, hh};}"
            : "=r"(wh1pH[0][j]) : "f"(x0), "f"(x1));
        asm("{.reg .f16 l, hh; cvt.rn.f16.f32 l, %1; cvt.rn.f16.f32 hh, %2; mov.b32 %0, {l, hh};}"
            : "=r"(wh1pH[1][j]) : "f"(y0), "f"(y1));
        acc[0][j] = 0ull; acc[1][j] = 0ull;
    }
    const float c0 = g_c6L[row0], c1 = g_c6L[row1];
    float lsum0 = 0.f, lsum1 = 0.f;

    // Per-lane adjacency, pipelined 2 steps ahead.
    const int* adjr0 = adj + (size_t)row0 * N_NODES + lane;
    const int* adjr1 = adj + (size_t)row1 * N_NODES + lane;
    int va0[2], va1[2];
    va0[0] = __ldg(adjr0);       va0[1] = __ldg(adjr0 + 32);
    va1[0] = __ldg(adjr1);       va1[1] = __ldg(adjr1 + 32);

    issue_tile(0, smem_u, tid);

#pragma unroll 1
    for (int t = 0; t < NTILES; ++t) {
        __syncthreads();
        if (t + 1 < NTILES) {
            issue_tile(t + 1, smem_u, tid);
            asm volatile("cp.async.wait_group 1;" ::: "memory");
        } else {
            asm volatile("cp.async.wait_group 0;" ::: "memory");
        }
        __syncthreads();

        const uint32_t sb = smem_u + (t & 1) * STAGE_BYTES;
        const float* sdk = (const float*)((const char*)smem2 + (t & 1) * STAGE_BYTES + DK_OFF);

#pragma unroll 4
        for (int step = 0; step < NSTEP; ++step) {
            const int kk = (step << 5) | lane;
            const int av0 = va0[step & 1], av1 = va1[step & 1];
            // prefetch adj for step+2 (wraps harmlessly at the end)
            const int nko = ((t << 8) + ((step + 2) << 5)) & (N_NODES - 1);
            va0[step & 1] = __ldg(adjr0 + nko);
            va1[step & 1] = __ldg(adjr1 + nko);
            const float dkv = sdk[kk];

            // ---- Score (fp16x2): 4 swizzled LDS.128 -> 16 fp16x2 ----
            uint32_t hh[16];
            {
                const uint32_t rb = sb + (uint32_t)(kk * 64);
                const int sw = (kk >> 1) & 3;
#pragma unroll
                for (int q = 0; q < 4; ++q)
                    asm volatile("ld.shared.v4.b32 {%0, %1, %2, %3}, [%4];"
                                 : "=r"(hh[4*q]), "=r"(hh[4*q+1]), "=r"(hh[4*q+2]), "=r"(hh[4*q+3])
                                 : "r"(rb + (uint32_t)((q ^ sw) << 4)));
            }
            uint32_t s0[4] = {0,0,0,0}, s1[4] = {0,0,0,0};
#pragma unroll
            for (int j = 0; j < 16; ++j) {
                uint32_t t0, t1;
                asm("add.rn.f16x2 %0, %1, %2;" : "=r"(t0) : "r"(wh1pH[0][j]), "r"(hh[j]));
                t0 &= 0x7fff7fffu;
                asm("fma.rn.f16x2 %0, %1, %2, %0;" : "+r"(s0[j & 3]) : "r"(a4LH[j]), "r"(t0));
                asm("add.rn.f16x2 %0, %1, %2;" : "=r"(t1) : "r"(wh1pH[1][j]), "r"(hh[j]));
                t1 &= 0x7fff7fffu;
                asm("fma.rn.f16x2 %0, %1, %2, %0;" : "+r"(s1[j & 3]) : "r"(a4LH[j]), "r"(t1));
            }
            float p0, p1;
            {
                uint32_t u; float lo, hi, e;
                asm("add.rn.f16x2 %0, %1, %2;" : "=r"(u) : "r"(s0[0]), "r"(s0[1]));
                asm("add.rn.f16x2 %0, %1, %2;" : "=r"(s0[2]) : "r"(s0[2]), "r"(s0[3]));
                asm("add.rn.f16x2 %0, %1, %2;" : "=r"(u) : "r"(u), "r"(s0[2]));
                asm("{.reg .f16 l, hh; mov.b32 {l, hh}, %2; cvt.f32.f16 %0, l; cvt.f32.f16 %1, hh;}"
                    : "=f"(lo), "=f"(hi) : "r"(u));
                e = (c0 + dkv) + (lo + hi);
                asm("ex2.approx.f32 %0, %1;" : "=f"(p0) : "f"(e));
                p0 = (av0 > 0) ? p0 : 0.f;
                asm("add.rn.f16x2 %0, %1, %2;" : "=r"(u) : "r"(s1[0]), "r"(s1[1]));
                asm("add.rn.f16x2 %0, %1, %2;" : "=r"(s1[2]) : "r"(s1[2]), "r"(s1[3]));
                asm("add.rn.f16x2 %0, %1, %2;" : "=r"(u) : "r"(u), "r"(s1[2]));
                asm("{.reg .f16 l, hh; mov.b32 {l, hh}, %2; cvt.f32.f16 %0, l; cvt.f32.f16 %1, hh;}"
                    : "=f"(lo), "=f"(hi) : "r"(u));
                e = (c1 + dkv) + (lo + hi);
                asm("ex2.approx.f32 %0, %1;" : "=f"(p1) : "f"(e));
                p1 = (av1 > 0) ? p1 : 0.f;
            }
            lsum0 += p0; lsum1 += p1;
            unsigned long long p20, p21;
            asm("mov.b64 %0, {%1, %1};" : "=l"(p20) : "f"(p0));
            asm("mov.b64 %0, {%1, %1};" : "=l"(p21) : "f"(p1));

            // ---- Aggregate (fp32x2): 8 swizzled LDS.128 ----
            const uint32_t rb1 = sb + SC_BYTES + (uint32_t)(kk << 7);
            const int sx = kk & 7;
#pragma unroll
            for (int f4 = 0; f4 < 8; ++f4) {
                unsigned long long v0, v1;
                asm volatile("ld.shared.v2.b64 {%0, %1}, [%2];"
                             : "=l"(v0), "=l"(v1) : "r"(rb1 + (uint32_t)((f4 ^ sx) << 4)));
                asm("fma.rn.f32x2 %0, %1, %2, %0;" : "+l"(acc[0][2*f4])   : "l"(p20), "l"(v0));
                asm("fma.rn.f32x2 %0, %1, %2, %0;" : "+l"(acc[0][2*f4+1]) : "l"(p20), "l"(v1));
                asm("fma.rn.f32x2 %0, %1, %2, %0;" : "+l"(acc[1][2*f4])   : "l"(p21), "l"(v0));
                asm("fma.rn.f32x2 %0, %1, %2, %0;" : "+l"(acc[1][2*f4+1]) : "l"(p21), "l"(v1));
            }
        }
    }

    // ---- Epilogue: cross-lane reduce, divide, ELU ----
    float L0 = lsum0, L1 = lsum1;
#pragma unroll
    for (int o = 16; o; o >>= 1) {
        L0 += __shfl_xor_sync(0xffffffffu, L0, o);
        L1 += __shfl_xor_sync(0xffffffffu, L1, o);
    }
    __syncthreads();
    float* red = smem2 + w * (32 * 33);
#pragma unroll 1
    for (int r = 0; r < 2; ++r) {
#pragma unroll
        for (int j = 0; j < 16; ++j) {
            float lo, hi;
            asm("mov.b64 {%0, %1}, %2;" : "=f"(lo), "=f"(hi) : "l"(acc[r][j]));
            red[lane * 33 + 2 * j]     = lo;
            red[lane * 33 + 2 * j + 1] = hi;
        }
        __syncwarp();
        float tot = 0.f;
#pragma unroll 8
        for (int jj = 0; jj < 32; ++jj) tot += red[jj * 33 + lane];
        const float L = r ? L1 : L0;
        const int row = r ? row1 : row0;
        const float hv = tot / L;
        out[row * OUT_F + lane] = hv > 0.f ? hv : expm1f(hv);
        __syncwarp();
    }
}

// ---------------------------------------------------------------------------
extern "C" void kernel_launch(void* const* d_in, const int* in_sizes, int n_in,
                              void* d_out, int out_size)
{
    const float* h   = (const float*)d_in[0];
    const int*   adj = (const int*)  d_in[1];
    const float* W   = (const float*)d_in[2];
    const float* a   = (const float*)d_in[3];
    float*       out = (float*)d_out;

    gat_gemm_kernel<<<N_NODES / 4, 128>>>(h, W, a);

    cudaFuncSetAttribute(gat_attn_kernel,
                         cudaFuncAttributeMaxDynamicSharedMemorySize, SMEM_BYTES);
    gat_attn_kernel<<<GRID, THREADS, SMEM_BYTES>>>(adj, a, out);
}